// round 2
// baseline (speedup 1.0000x reference)
#include <cuda_runtime.h>

// UVLearner: uv[b,q,:] = softmax_k( (x[b,:,q] . y[b,:,k]) * c^-0.5 ) @ grid[k,:]
// then uv/64*2-1.  x,y: (4,128,64,64) fp32.  out: (4,64,64,2) fp32.
//
// Fused flash-style kernel: per block 128 queries, stream 4096 keys in
// 128-key tiles; logits GEMM in registers (8x8 frags, stride-16 mapping,
// conflict-free smem), exp + coordinate-weighted accumulation in epilogue.

#define CD 128   // channels (reduction dim)
#define QT 128   // queries per block
#define KT 128   // keys per tile

__global__ __launch_bounds__(256, 1)
void uv_kernel(const float* __restrict__ x, const float* __restrict__ y,
               float* __restrict__ out) {
    extern __shared__ float sm[];
    float* xs = sm;            // [CD][QT], pre-scaled by log2(e)*c^-0.5
    float* ys = sm + CD * QT;  // [CD][KT]

    const int b  = blockIdx.x >> 5;          // 32 q-tiles per batch
    const int q0 = (blockIdx.x & 31) * QT;
    const float* xb = x + (size_t)b * CD * 4096 + q0;
    const float* yb = y + (size_t)b * CD * 4096;

    const int tid = threadIdx.x;
    const int tx  = tid & 15;   // key-fragment lane  (16)
    const int ty  = tid >> 4;   // query-fragment lane (16)

    // log2(e) / sqrt(128): folds softmax scale + exp2 conversion into x once.
    const float K2E = 0.12754245778362382f;

    // Load + prescale the x tile (reused across all 32 key tiles).
    for (int i = tid; i < CD * QT / 4; i += 256) {
        int c  = i >> 5;           // QT/4 == 32 float4 per row
        int q4 = (i & 31) << 2;
        float4 v = *(const float4*)(xb + c * 4096 + q4);
        v.x *= K2E; v.y *= K2E; v.z *= K2E; v.w *= K2E;
        *(float4*)(xs + c * QT + q4) = v;
    }

    float den[8], n0[8], n1[8];
    #pragma unroll
    for (int j = 0; j < 8; j++) { den[j] = 0.f; n0[j] = 0.f; n1[j] = 0.f; }

    for (int kt0 = 0; kt0 < 4096; kt0 += KT) {
        __syncthreads();   // protects xs (first iter) and previous ys use
        for (int i = tid; i < CD * KT / 4; i += 256) {
            int c  = i >> 5;
            int k4 = (i & 31) << 2;
            *(float4*)(ys + c * KT + k4) =
                *(const float4*)(yb + c * 4096 + kt0 + k4);
        }
        __syncthreads();

        float s[8][8];
        #pragma unroll
        for (int j = 0; j < 8; j++)
            #pragma unroll
            for (int i = 0; i < 8; i++) s[j][i] = 0.f;

        #pragma unroll 4
        for (int c = 0; c < CD; c++) {
            float xf[8], yf[8];
            // broadcast loads (addr depends only on ty / tx) -> conflict-free
            #pragma unroll
            for (int j = 0; j < 8; j++) xf[j] = xs[c * QT + ty + 16 * j];
            #pragma unroll
            for (int i = 0; i < 8; i++) yf[i] = ys[c * KT + tx + 16 * i];
            #pragma unroll
            for (int j = 0; j < 8; j++)
                #pragma unroll
                for (int i = 0; i < 8; i++)
                    s[j][i] = fmaf(xf[j], yf[i], s[j][i]);
        }

        // Softmax accumulation. Logits ~N(0,1): no running max needed
        // (|s| <~ 9 in exp2 domain, safely inside fp32 range).
        #pragma unroll
        for (int i = 0; i < 8; i++) {
            int k = kt0 + tx + 16 * i;
            float g0 = (float)(k & 63) + 0.5f;   // col + 0.5
            float g1 = (float)(k >> 6) + 0.5f;   // row + 0.5
            #pragma unroll
            for (int j = 0; j < 8; j++) {
                float e = exp2f(s[j][i]);        // MUFU.EX2
                den[j] += e;
                n0[j]  = fmaf(e, g0, n0[j]);
                n1[j]  = fmaf(e, g1, n1[j]);
            }
        }
    }

    // Reduce (den, n0, n1) across the 16 tx lanes (half-warp segments).
    #pragma unroll
    for (int j = 0; j < 8; j++) {
        #pragma unroll
        for (int off = 8; off > 0; off >>= 1) {
            den[j] += __shfl_xor_sync(0xffffffffu, den[j], off, 16);
            n0[j]  += __shfl_xor_sync(0xffffffffu, n0[j],  off, 16);
            n1[j]  += __shfl_xor_sync(0xffffffffu, n1[j],  off, 16);
        }
    }

    if (tx == 0) {
        #pragma unroll
        for (int j = 0; j < 8; j++) {
            int q = q0 + ty + 16 * j;
            float inv = 1.0f / (32.0f * den[j]);   // (uv/64)*2 - 1
            float* o = out + ((size_t)b * 4096 + q) * 2;
            o[0] = n0[j] * inv - 1.0f;
            o[1] = n1[j] * inv - 1.0f;
        }
    }
}

extern "C" void kernel_launch(void* const* d_in, const int* in_sizes, int n_in,
                              void* d_out, int out_size) {
    const float* x = (const float*)d_in[0];
    const float* y = (const float*)d_in[1];
    float* out = (float*)d_out;

    const size_t smem = (size_t)(CD * QT + CD * KT) * sizeof(float);  // 128 KB
    cudaFuncSetAttribute(uv_kernel,
                         cudaFuncAttributeMaxDynamicSharedMemorySize,
                         (int)smem);
    uv_kernel<<<128, 256, smem>>>(x, y, out);
}

// round 6
// speedup vs baseline: 1.2244x; 1.2244x over previous
#include <cuda_runtime.h>

// UVLearner: uv[b,q,:] = softmax_k( (x[b,:,q].y[b,:,k]) * c^-0.5 ) @ grid[k,:],
// then uv/64*2-1.  x,y: (4,128,64,64) fp32.  out: (4,64,64,2) fp32.
//
// R3: same as R2 (packed fp32 math via fma.rn.f32x2, float4 fragment loads,
// cp.async double buffering) with the exp fixed to explicit MUFU via
// ex2.approx.f32 inline PTX.

#define CD 128   // channels (reduction)
#define QT 128   // queries per block
#define KT 128   // keys per tile

__device__ __forceinline__ unsigned long long pk2(float lo, float hi) {
    unsigned long long r;
    asm("mov.b64 %0, {%1, %2};" : "=l"(r) : "f"(lo), "f"(hi));
    return r;
}
__device__ __forceinline__ void upk2(float& lo, float& hi, unsigned long long v) {
    asm("mov.b64 {%0, %1}, %2;" : "=f"(lo), "=f"(hi) : "l"(v));
}
__device__ __forceinline__ unsigned long long ffma2(unsigned long long a,
                                                    unsigned long long b,
                                                    unsigned long long c) {
    unsigned long long d;
    asm("fma.rn.f32x2 %0, %1, %2, %3;" : "=l"(d) : "l"(a), "l"(b), "l"(c));
    return d;
}
__device__ __forceinline__ float ex2(float a) {
    float r;
    asm("ex2.approx.f32 %0, %1;" : "=f"(r) : "f"(a));
    return r;
}

__global__ __launch_bounds__(256, 1)
void uv_kernel(const float* __restrict__ x, const float* __restrict__ y,
               float* __restrict__ out) {
    extern __shared__ float sm[];
    float* xs = sm;            // [CD][QT], pre-scaled by log2(e)*c^-0.5
    float* ys = sm + CD * QT;  // 2 x [CD][KT] double buffer

    const int b  = blockIdx.x >> 5;
    const int q0 = (blockIdx.x & 31) * QT;
    const float* xb = x + (size_t)b * CD * 4096 + q0;
    const float* yb = y + (size_t)b * CD * 4096;

    const int tid = threadIdx.x;
    const int tx  = tid & 15;   // k-lane
    const int ty  = tid >> 4;   // q-lane

    const float K2E = 0.12754245778362382f;  // log2(e)/sqrt(128)

    // x tile: load + prescale once.
    for (int i = tid; i < CD * QT / 4; i += 256) {
        int c  = i >> 5;
        int q4 = (i & 31) << 2;
        float4 v = *(const float4*)(xb + c * 4096 + q4);
        v.x *= K2E; v.y *= K2E; v.z *= K2E; v.w *= K2E;
        *(float4*)(xs + c * QT + q4) = v;
    }

    // cp.async prefetch of one 128-key y tile into buffer `buf`.
    auto prefetch = [&](int kt0, int buf) {
        float* dst = ys + buf * CD * KT;
        #pragma unroll 4
        for (int i = tid; i < CD * KT / 4; i += 256) {
            int c  = i >> 5;
            int k4 = (i & 31) << 2;
            unsigned ds = (unsigned)__cvta_generic_to_shared(dst + c * KT + k4);
            const float* src = yb + c * 4096 + kt0 + k4;
            asm volatile("cp.async.ca.shared.global [%0], [%1], 16;"
                         :: "r"(ds), "l"(src));
        }
    };

    // accumulators: [jj][jp], f32x2 over the two k-parity halves
    unsigned long long den2[2][4], n02[2][4], n12[2][4];
    #pragma unroll
    for (int jj = 0; jj < 2; jj++)
        #pragma unroll
        for (int jp = 0; jp < 4; jp++) {
            den2[jj][jp] = 0ull; n02[jj][jp] = 0ull; n12[jj][jp] = 0ull;
        }

    const unsigned long long one2 = pk2(1.0f, 1.0f);
    unsigned long long g0p[2];  // col coords: tile-invariant (k & 63 = 4*tx + p)
    #pragma unroll
    for (int pp = 0; pp < 2; pp++)
        g0p[pp] = pk2((float)(4 * tx + 2 * pp) + 0.5f,
                      (float)(4 * tx + 2 * pp + 1) + 0.5f);

    prefetch(0, 0);
    asm volatile("cp.async.commit_group;");

    for (int t = 0; t < 32; t++) {
        asm volatile("cp.async.wait_group 0;" ::: "memory");
        __syncthreads();
        if (t + 1 < 32) {
            prefetch((t + 1) * KT, (t + 1) & 1);
            asm volatile("cp.async.commit_group;");
        }
        const float* yt = ys + (t & 1) * CD * KT;

        // logit fragments: [jj][jp][ii][pp] over (q, k) pairs
        unsigned long long s2[2][4][2][2];
        #pragma unroll
        for (int jj = 0; jj < 2; jj++)
            #pragma unroll
            for (int jp = 0; jp < 4; jp++)
                #pragma unroll
                for (int ii = 0; ii < 2; ii++) {
                    s2[jj][jp][ii][0] = 0ull; s2[jj][jp][ii][1] = 0ull;
                }

        #pragma unroll 2
        for (int c = 0; c < CD; c++) {
            float4 xv[2], yv[2];
            xv[0] = *(const float4*)(xs + c * QT + 4 * ty);
            xv[1] = *(const float4*)(xs + c * QT + 4 * ty + 64);
            yv[0] = *(const float4*)(yt + c * KT + 4 * tx);
            yv[1] = *(const float4*)(yt + c * KT + 4 * tx + 64);

            unsigned long long xd[2][4], yp[2][2];
            #pragma unroll
            for (int jj = 0; jj < 2; jj++) {
                xd[jj][0] = pk2(xv[jj].x, xv[jj].x);
                xd[jj][1] = pk2(xv[jj].y, xv[jj].y);
                xd[jj][2] = pk2(xv[jj].z, xv[jj].z);
                xd[jj][3] = pk2(xv[jj].w, xv[jj].w);
            }
            #pragma unroll
            for (int ii = 0; ii < 2; ii++) {
                yp[ii][0] = pk2(yv[ii].x, yv[ii].y);
                yp[ii][1] = pk2(yv[ii].z, yv[ii].w);
            }
            #pragma unroll
            for (int jj = 0; jj < 2; jj++)
                #pragma unroll
                for (int jp = 0; jp < 4; jp++)
                    #pragma unroll
                    for (int ii = 0; ii < 2; ii++)
                        #pragma unroll
                        for (int pp = 0; pp < 2; pp++)
                            s2[jj][jp][ii][pp] =
                                ffma2(xd[jj][jp], yp[ii][pp], s2[jj][jp][ii][pp]);
        }

        // epilogue: exp2 + packed coordinate accumulation.
        // k = 128t + 4tx + 64ii + 2pp + {0,1}; row = k>>6 = 2t + ii.
        unsigned long long g1p[2];
        g1p[0] = pk2((float)(2 * t) + 0.5f, (float)(2 * t) + 0.5f);
        g1p[1] = pk2((float)(2 * t + 1) + 0.5f, (float)(2 * t + 1) + 0.5f);

        #pragma unroll
        for (int jj = 0; jj < 2; jj++)
            #pragma unroll
            for (int jp = 0; jp < 4; jp++)
                #pragma unroll
                for (int ii = 0; ii < 2; ii++)
                    #pragma unroll
                    for (int pp = 0; pp < 2; pp++) {
                        float a, bb;
                        upk2(a, bb, s2[jj][jp][ii][pp]);
                        unsigned long long e2 = pk2(ex2(a), ex2(bb));
                        den2[jj][jp] = ffma2(e2, one2,    den2[jj][jp]);
                        n02[jj][jp]  = ffma2(e2, g0p[pp], n02[jj][jp]);
                        n12[jj][jp]  = ffma2(e2, g1p[ii], n12[jj][jp]);
                    }
    }

    // fold pair halves, then reduce across the 16 tx lanes.
    #pragma unroll
    for (int jj = 0; jj < 2; jj++)
        #pragma unroll
        for (int jp = 0; jp < 4; jp++) {
            float dl, dh, al, ah, bl, bh;
            upk2(dl, dh, den2[jj][jp]);
            upk2(al, ah, n02[jj][jp]);
            upk2(bl, bh, n12[jj][jp]);
            float den = dl + dh, n0 = al + ah, n1 = bl + bh;
            #pragma unroll
            for (int off = 8; off > 0; off >>= 1) {
                den += __shfl_xor_sync(0xffffffffu, den, off, 16);
                n0  += __shfl_xor_sync(0xffffffffu, n0,  off, 16);
                n1  += __shfl_xor_sync(0xffffffffu, n1,  off, 16);
            }
            if (tx == 0) {
                int q = q0 + 4 * ty + 64 * jj + jp;
                float inv = 1.0f / (32.0f * den);   // (uv/64)*2 - 1
                float* o = out + ((size_t)b * 4096 + q) * 2;
                o[0] = n0 * inv - 1.0f;
                o[1] = n1 * inv - 1.0f;
            }
        }
}

extern "C" void kernel_launch(void* const* d_in, const int* in_sizes, int n_in,
                              void* d_out, int out_size) {
    const float* x = (const float*)d_in[0];
    const float* y = (const float*)d_in[1];
    float* out = (float*)d_out;

    const size_t smem = (size_t)(CD * QT + 2 * CD * KT) * sizeof(float); // 192KB
    cudaFuncSetAttribute(uv_kernel,
                         cudaFuncAttributeMaxDynamicSharedMemorySize,
                         (int)smem);
    uv_kernel<<<128, 256, smem>>>(x, y, out);
}

// round 10
// speedup vs baseline: 3.0252x; 2.4708x over previous
#include <cuda_runtime.h>
#include <cuda_bf16.h>
#include <cstdint>

// UVLearner via warp-level bf16 mma.sync (HMMA): S = X^T Y with 3-way bf16
// split (hi*hi + hi*lo + lo*hi), fp32 accum, fused softmax-weighted coord sum.
// tcgen05 is unavailable (harness targets compute_103 PTX, no 'a' features).
// R8 fix: grid column = key & 63 (the 64-key warp half folds into the ROW).

#define XROW 272               // 256B row + 16B pad -> conflict-free LDSM
#define SM_XH 0u
#define SM_XL 34816u
#define SM_Y  69632u           // + buf*69632 ; in buf: hi +0, lo +34816
#define SM_RED 208896u         // 2*128*3 floats
#define SMEM_TOTAL 211968u

__device__ uint4 g_yh[4][4096][16];   // y hi-split [b][key][c/8] bf16x8
__device__ uint4 g_yl[4][4096][16];   // y lo-split

__device__ __forceinline__ float ex2(float a) {
    float r; asm("ex2.approx.f32 %0, %1;" : "=f"(r) : "f"(a)); return r;
}
#define LDSM4(r, a) \
    asm volatile("ldmatrix.sync.aligned.m8n8.x4.shared.b16 {%0,%1,%2,%3}, [%4];" \
        : "=r"((r)[0]), "=r"((r)[1]), "=r"((r)[2]), "=r"((r)[3]) : "r"(a))

__device__ __forceinline__ void mma16816(float* c, const uint32_t* a,
                                         const uint32_t* b) {
    asm volatile(
        "mma.sync.aligned.m16n8k16.row.col.f32.bf16.bf16.f32 "
        "{%0,%1,%2,%3}, {%4,%5,%6,%7}, {%8,%9}, {%0,%1,%2,%3};"
        : "+f"(c[0]), "+f"(c[1]), "+f"(c[2]), "+f"(c[3])
        : "r"(a[0]), "r"(a[1]), "r"(a[2]), "r"(a[3]), "r"(b[0]), "r"(b[1]));
}
__device__ __forceinline__ uint32_t pkbf(float v0, float v1) {
    __nv_bfloat16 b0 = __float2bfloat16(v0), b1 = __float2bfloat16(v1);
    return ((uint32_t)__bfloat16_as_ushort(b1) << 16) | __bfloat16_as_ushort(b0);
}

// ---------- pre-pass: y -> [b][k][c] bf16 hi/lo ----------
__global__ __launch_bounds__(256)
void ytrans_kernel(const float* __restrict__ y) {
    int i = blockIdx.x * 256 + threadIdx.x;   // 4 * 16 * 4096
    int k  = i & 4095;
    int cg = (i >> 12) & 15;
    int b  = i >> 16;
    const float* src = y + ((size_t)(b * 128 + cg * 8)) * 4096 + k;
    uint32_t h[4], l[4];
    #pragma unroll
    for (int j = 0; j < 4; j++) {
        float v0 = src[(size_t)(2 * j) * 4096];
        float v1 = src[(size_t)(2 * j + 1) * 4096];
        __nv_bfloat16 h0 = __float2bfloat16(v0);
        __nv_bfloat16 h1 = __float2bfloat16(v1);
        float r0 = v0 - __bfloat162float(h0);
        float r1 = v1 - __bfloat162float(h1);
        h[j] = ((uint32_t)__bfloat16_as_ushort(h1) << 16) | __bfloat16_as_ushort(h0);
        l[j] = pkbf(r0, r1);
    }
    g_yh[b][k][cg] = make_uint4(h[0], h[1], h[2], h[3]);
    g_yl[b][k][cg] = make_uint4(l[0], l[1], l[2], l[3]);
}

// ---------- main kernel ----------
__global__ __launch_bounds__(256, 1)
void uv_kernel(const float* __restrict__ x, float* __restrict__ out) {
    extern __shared__ char smem[];
    const uint32_t sb = (uint32_t)__cvta_generic_to_shared(smem);
    const int tid = threadIdx.x, wid = tid >> 5, lane = tid & 31;
    const int bb = blockIdx.x >> 5, q0 = (blockIdx.x & 31) * 128;
    const float* xb = x + (size_t)bb * 128 * 4096 + q0;
    const float K2E = 0.12754245778362382f;   // log2(e)/sqrt(128)

    // x prologue: scale, split, store [q][c] bf16 rows (hi/lo)
    for (int i = tid; i < 8192; i += 256) {
        int c = (i >> 7) * 2, q = i & 127;
        float v0 = xb[(size_t)c * 4096 + q] * K2E;
        float v1 = xb[(size_t)(c + 1) * 4096 + q] * K2E;
        __nv_bfloat16 h0 = __float2bfloat16(v0), h1 = __float2bfloat16(v1);
        float r0 = v0 - __bfloat162float(h0), r1 = v1 - __bfloat162float(h1);
        uint32_t hp = ((uint32_t)__bfloat16_as_ushort(h1) << 16) | __bfloat16_as_ushort(h0);
        uint32_t lp = pkbf(r0, r1);
        *(uint32_t*)(smem + SM_XH + q * XROW + c * 2) = hp;
        *(uint32_t*)(smem + SM_XL + q * XROW + c * 2) = lp;
    }

    auto prefetch = [&](int t) {
        uint32_t dst0 = sb + SM_Y + (uint32_t)(t & 1) * 69632u;
        for (int i = tid; i < 4096; i += 256) {
            int sp = i >> 11, r = (i >> 4) & 127, j = i & 15;
            uint32_t d = dst0 + (uint32_t)sp * 34816u + (uint32_t)(r * XROW + j * 16);
            const uint4* s = sp ? &g_yl[bb][t * 128 + r][j] : &g_yh[bb][t * 128 + r][j];
            asm volatile("cp.async.ca.shared.global [%0], [%1], 16;"
                         :: "r"(d), "l"(s));
        }
    };

    // warp tiling: m = 32 q (2 m16), n = 64 k (8 n8); warps 4q x 2k
    const int mq = (wid & 3) * 32, nb = (wid >> 2) * 64;
    // A ldmatrix addrs: row = mq + mtile*16 + lane%16, colb = ks*32 + (lane/16)*16
    const uint32_t aOff = (uint32_t)((mq + (lane & 15)) * XROW + (lane >> 4) * 16);
    // B ldmatrix addrs: row = nb + jp*16 + (lane/16)*8 + lane%8,
    //                   colb = ks*32 + ((lane>>3)&1)*16
    const uint32_t bOff = (uint32_t)((nb + (lane >> 4) * 8 + (lane & 7)) * XROW
                                     + ((lane >> 3) & 1) * 16);

    float den[4], n0a[4], n1a[4];
    #pragma unroll
    for (int a = 0; a < 4; a++) { den[a] = 0.f; n0a[a] = 0.f; n1a[a] = 0.f; }

    prefetch(0);
    asm volatile("cp.async.commit_group;");
    __syncthreads();   // x tile visible to all warps

    for (int t = 0; t < 32; t++) {
        if (t + 1 < 32) {
            prefetch(t + 1);
            asm volatile("cp.async.commit_group;");
            asm volatile("cp.async.wait_group 1;" ::: "memory");
        } else {
            asm volatile("cp.async.wait_group 0;" ::: "memory");
        }
        __syncthreads();
        const uint32_t ybuf = sb + SM_Y + (uint32_t)(t & 1) * 69632u;
        const uint32_t bhB = ybuf + bOff, blB = bhB + 34816u;
        const uint32_t ahB = sb + SM_XH + aOff, alB = sb + SM_XL + aOff;

        float cA[2][8][4];
        #pragma unroll
        for (int m = 0; m < 2; m++)
            #pragma unroll
            for (int j = 0; j < 8; j++)
                #pragma unroll
                for (int e = 0; e < 4; e++) cA[m][j][e] = 0.f;

        #pragma unroll
        for (int ks = 0; ks < 8; ks++) {
            uint32_t ah[2][4], al[2][4];
            LDSM4(ah[0], ahB + ks * 32);
            LDSM4(ah[1], ahB + ks * 32 + 16 * XROW);
            LDSM4(al[0], alB + ks * 32);
            LDSM4(al[1], alB + ks * 32 + 16 * XROW);
            #pragma unroll
            for (int jp = 0; jp < 4; jp++) {
                uint32_t bh[4], bl[4];
                LDSM4(bh, bhB + jp * (16 * XROW) + ks * 32);
                LDSM4(bl, blB + jp * (16 * XROW) + ks * 32);
                #pragma unroll
                for (int m = 0; m < 2; m++)
                    #pragma unroll
                    for (int jn = 0; jn < 2; jn++) {
                        float* cc = cA[m][2 * jp + jn];
                        mma16816(cc, ah[m], bh + 2 * jn);   // hi*hi
                        mma16816(cc, ah[m], bl + 2 * jn);   // hi*lo
                        mma16816(cc, al[m], bh + 2 * jn);   // lo*hi
                    }
            }
        }
        __syncthreads();   // y buffer free before its overwrite next iter

        // epilogue: exp2 + coordinate accumulation.
        // key_local = nb + j*8 + 2*(lane&3)+{0,1}; grid col = key_local & 63
        // (nb is 0 or 64 -> drops out of the column), grid row = 2t + (nb>>6).
        const float rowc = (float)(2 * t + (wid >> 2)) + 0.5f;
        #pragma unroll
        for (int m = 0; m < 2; m++)
            #pragma unroll
            for (int h = 0; h < 2; h++) {
                float dt = 0.f, n0t = 0.f;
                #pragma unroll
                for (int j = 0; j < 8; j++) {
                    float e0 = ex2(cA[m][j][2 * h]);
                    float e1 = ex2(cA[m][j][2 * h + 1]);
                    float k0 = (float)(j * 8 + 2 * (lane & 3)) + 0.5f;
                    dt += e0 + e1;
                    n0t = fmaf(e0, k0, n0t);
                    n0t = fmaf(e1, k0 + 1.0f, n0t);
                }
                int a = m * 2 + h;
                den[a] += dt;
                n0a[a] += n0t;
                n1a[a] = fmaf(dt, rowc, n1a[a]);
            }
    }

    // reduce across the 4 lanes of each row group
    #pragma unroll
    for (int a = 0; a < 4; a++) {
        #pragma unroll
        for (int off = 1; off < 4; off <<= 1) {
            den[a] += __shfl_xor_sync(0xffffffffu, den[a], off, 4);
            n0a[a] += __shfl_xor_sync(0xffffffffu, n0a[a], off, 4);
            n1a[a] += __shfl_xor_sync(0xffffffffu, n1a[a], off, 4);
        }
    }
    float* red = (float*)(smem + SM_RED);
    if ((lane & 3) == 0) {
        #pragma unroll
        for (int a = 0; a < 4; a++) {
            int qrow = mq + (a >> 1) * 16 + (lane >> 2) + (a & 1) * 8;
            int base = ((wid >> 2) * 128 + qrow) * 3;
            red[base] = den[a]; red[base + 1] = n0a[a]; red[base + 2] = n1a[a];
        }
    }
    __syncthreads();

    if (tid < 128) {
        float d  = red[tid * 3]     + red[(128 + tid) * 3];
        float n0 = red[tid * 3 + 1] + red[(128 + tid) * 3 + 1];
        float n1 = red[tid * 3 + 2] + red[(128 + tid) * 3 + 2];
        float inv = 1.0f / (32.0f * d);   // (uv/64)*2 - 1
        float* o = out + ((size_t)bb * 4096 + q0 + tid) * 2;
        o[0] = n0 * inv - 1.0f;
        o[1] = n1 * inv - 1.0f;
    }
}

extern "C" void kernel_launch(void* const* d_in, const int* in_sizes, int n_in,
                              void* d_out, int out_size) {
    const float* x = (const float*)d_in[0];
    const float* y = (const float*)d_in[1];
    float* out = (float*)d_out;

    cudaFuncSetAttribute(uv_kernel,
                         cudaFuncAttributeMaxDynamicSharedMemorySize,
                         (int)SMEM_TOTAL);
    ytrans_kernel<<<1024, 256>>>(y);
    uv_kernel<<<128, 256, SMEM_TOTAL>>>(x, out);
}